// round 12
// baseline (speedup 1.0000x reference)
#include <cuda_runtime.h>
#include <cuda_fp16.h>
#include <cstdint>

// Problem constants
#define B_ 2
#define L_ 4096
#define D_ 512
#define H_ 8
#define BH_ (B_ * H_)

// E is scaled by 2^-6 before fp16 conversion (exp(S/8) can reach ~7e4 > fp16 max);
// the x64 is folded back into the O normalization.
#define ESCALE 0.015625f
#define EUNSCALE 64.0f

// ---------------------------------------------------------------------------
// Static device scratch (allocation-free).
// ---------------------------------------------------------------------------
__device__ __half g_Qhi[BH_ * L_ * 64];
__device__ __half g_Qlo[BH_ * L_ * 64];
__device__ __half g_Khi[BH_ * L_ * 64];
__device__ __half g_Klo[BH_ * L_ * 64];
__device__ __half g_Vhi[BH_ * L_ * 64];
__device__ __half g_Vlo[BH_ * L_ * 64];
__device__ __half g_Xhi[3][B_ * L_ * D_];   // fp16 hi/lo splits of inputs q,k,v
__device__ __half g_Xlo[3][B_ * L_ * D_];
__device__ __half g_Whi[3][D_ * D_];        // splits of wq,wk,wv
__device__ __half g_Wlo[3][D_ * D_];
__device__ float  g_O[BH_ * L_ * 64];       // normalized context [b][h][l][dv]
__device__ float  g_rowsum[BH_ * L_];       // softmax denominators [(h*B+b)][l]

// ---------------------------------------------------------------------------
// mma.sync / ldmatrix / cp.async helpers (base sm_103 features, no 'a')
// ---------------------------------------------------------------------------
__device__ __forceinline__ uint32_t smem_u32(const void* p) {
    uint32_t a;
    asm("{ .reg .u64 t; cvta.to.shared.u64 t, %1; cvt.u32.u64 %0, t; }"
        : "=r"(a) : "l"(p));
    return a;
}
__device__ __forceinline__ void ldm4(uint32_t* r, uint32_t a) {
    asm volatile("ldmatrix.sync.aligned.m8n8.x4.shared.b16 {%0,%1,%2,%3}, [%4];"
        : "=r"(r[0]), "=r"(r[1]), "=r"(r[2]), "=r"(r[3]) : "r"(a));
}
__device__ __forceinline__ void ldm4t(uint32_t* r, uint32_t a) {
    asm volatile("ldmatrix.sync.aligned.m8n8.x4.trans.shared.b16 {%0,%1,%2,%3}, [%4];"
        : "=r"(r[0]), "=r"(r[1]), "=r"(r[2]), "=r"(r[3]) : "r"(a));
}
__device__ __forceinline__ void mma16(float* d, const uint32_t* a, const uint32_t* b) {
    asm volatile("mma.sync.aligned.m16n8k16.row.col.f32.f16.f16.f32 "
        "{%0,%1,%2,%3}, {%4,%5,%6,%7}, {%8,%9}, {%0,%1,%2,%3};"
        : "+f"(d[0]), "+f"(d[1]), "+f"(d[2]), "+f"(d[3])
        : "r"(a[0]), "r"(a[1]), "r"(a[2]), "r"(a[3]), "r"(b[0]), "r"(b[1]));
}
__device__ __forceinline__ void cp16(uint32_t s, const void* g) {
    asm volatile("cp.async.cg.shared.global [%0], [%1], 16;" :: "r"(s), "l"(g) : "memory");
}
#define CP_COMMIT()  asm volatile("cp.async.commit_group;" ::: "memory")
#define CP_WAIT(n)   asm volatile("cp.async.wait_group %0;" :: "n"(n) : "memory")

// split a float pair into fp16 hi / lo packed b32 regs
__device__ __forceinline__ void split2(float a, float b, uint32_t& hi, uint32_t& lo) {
    __half ha = __float2half_rn(a), hb = __float2half_rn(b);
    __half la = __float2half_rn(a - __half2float(ha));
    __half lb = __float2half_rn(b - __half2float(hb));
    __half2 h = __halves2half2(ha, hb), l = __halves2half2(la, lb);
    hi = *(uint32_t*)&h; lo = *(uint32_t*)&l;
}

#define PITCH 72                         // halfs per smem row (144B, 16B-mult)
#define TILE_B (128 * PITCH * 2)         // 18432 bytes per 128x64 fp16 tile

// ---------------------------------------------------------------------------
// split_kernel: fp32 -> fp16 hi/lo (grid-stride over float4)
// ---------------------------------------------------------------------------
__global__ __launch_bounds__(256) void split_kernel(
    const float* __restrict__ src, __half* __restrict__ hi,
    __half* __restrict__ lo, int n4)
{
    int i = blockIdx.x * blockDim.x + threadIdx.x;
    if (i >= n4) return;
    float4 v = ((const float4*)src)[i];
    __half h0 = __float2half_rn(v.x), h1 = __float2half_rn(v.y);
    __half h2 = __float2half_rn(v.z), h3 = __float2half_rn(v.w);
    __half l0 = __float2half_rn(v.x - __half2float(h0));
    __half l1 = __float2half_rn(v.y - __half2float(h1));
    __half l2 = __float2half_rn(v.z - __half2float(h2));
    __half l3 = __float2half_rn(v.w - __half2float(h3));
    __half2* hp = (__half2*)&hi[4 * (size_t)i];
    __half2* lp = (__half2*)&lo[4 * (size_t)i];
    hp[0] = __halves2half2(h0, h1); hp[1] = __halves2half2(h2, h3);
    lp[0] = __halves2half2(l0, l1); lp[1] = __halves2half2(l2, l3);
}

// ---------------------------------------------------------------------------
// proj_mma: C = X @ W.T + bias -> fp16 hi/lo splits in head-major layout.
// M=8192, N=512, K=512.  CTA: 128x128, 8 warps (16 rows x 128 cols each).
// Same fragment scheme as attn GEMM1 (proven): 3-term fp16 hi/lo split.
// smem: Xhi,Xlo,Whi,Wlo 128x64-half tiles, double buffered + bias slice.
// ---------------------------------------------------------------------------
#define PROJ_SMEM (8 * TILE_B + 512)

__global__ __launch_bounds__(256) void proj_mma(const float* __restrict__ bias, int sel)
{
    extern __shared__ __align__(128) char smem[];
    const uint32_t sb = smem_u32(smem);
    float* sbias = (float*)(smem + 8 * TILE_B);

    const __half* Xhi = g_Xhi[sel];
    const __half* Xlo = g_Xlo[sel];
    const __half* Whi = g_Whi[sel];
    const __half* Wlo = g_Wlo[sel];
    __half* Ohi = (sel == 0) ? g_Qhi : (sel == 1) ? g_Khi : g_Vhi;
    __half* Olo = (sel == 0) ? g_Qlo : (sel == 1) ? g_Klo : g_Vlo;

    const int n0 = blockIdx.x * 128;
    const int m0 = blockIdx.y * 128;
    const int tid = threadIdx.x, wid = tid >> 5, lane = tid & 31;
    const int r0 = wid * 16;

    if (tid < 128) sbias[tid] = bias[n0 + tid];

    // ldmatrix offsets (identical scheme to attn GEMM1)
    const int l7 = lane & 7;
    const uint32_t a_off = (uint32_t)((r0 + l7 + ((lane & 8) ? 8 : 0)) * PITCH
                                      + ((lane & 16) ? 8 : 0)) * 2;
    const uint32_t bk_off = (uint32_t)((l7 + ((lane & 16) ? 8 : 0)) * PITCH
                                       + ((lane & 8) ? 8 : 0)) * 2;

    float S[16][4];
#pragma unroll
    for (int i = 0; i < 16; i++)
#pragma unroll
        for (int j = 0; j < 4; j++) S[i][j] = 0.f;

    // prefetch: per buffer stage load Xhi,Xlo (rows m0+), Whi,Wlo (rows n0+)
    auto prefetch = [&](int kc, uint32_t buf) {
#pragma unroll
        for (int t = 0; t < 4; t++) {
            int i = tid + t * 256;             // 1024 chunks per tensor
            int row = i >> 3, c8 = i & 7;
            uint32_t so = (uint32_t)(row * PITCH + c8 * 8) * 2;
            size_t xg = ((size_t)(m0 + row) * 512 + kc * 64 + c8 * 8) * 2;
            size_t wg = ((size_t)(n0 + row) * 512 + kc * 64 + c8 * 8) * 2;
            cp16(buf + 0 * TILE_B + so, (const char*)Xhi + xg);
            cp16(buf + 1 * TILE_B + so, (const char*)Xlo + xg);
            cp16(buf + 2 * TILE_B + so, (const char*)Whi + wg);
            cp16(buf + 3 * TILE_B + so, (const char*)Wlo + wg);
        }
    };

    prefetch(0, sb);
    CP_COMMIT();

    for (int kc = 0; kc < 8; kc++) {
        const uint32_t buf = sb + ((kc & 1) ? 4 * TILE_B : 0);
        if (kc < 7) {
            prefetch(kc + 1, sb + (((kc + 1) & 1) ? 4 * TILE_B : 0));
            CP_COMMIT();
            CP_WAIT(1);
        } else {
            CP_WAIT(0);
        }
        __syncthreads();

#pragma unroll
        for (int ks = 0; ks < 4; ks++) {
            const uint32_t kc2 = (uint32_t)(ks * 16) * 2;
            uint32_t ah[4], al[4];
            ldm4(ah, buf + 0 * TILE_B + a_off + kc2);
            ldm4(al, buf + 1 * TILE_B + a_off + kc2);
#pragma unroll
            for (int np = 0; np < 8; np++) {
                uint32_t bh4[4], bl4[4];
                uint32_t boff = bk_off + (uint32_t)(np * 16 * PITCH) * 2 + kc2;
                ldm4(bh4, buf + 2 * TILE_B + boff);
                ldm4(bl4, buf + 3 * TILE_B + boff);
                mma16(S[2 * np],     ah, bh4 + 0);
                mma16(S[2 * np],     ah, bl4 + 0);
                mma16(S[2 * np],     al, bh4 + 0);
                mma16(S[2 * np + 1], ah, bh4 + 2);
                mma16(S[2 * np + 1], ah, bl4 + 2);
                mma16(S[2 * np + 1], al, bh4 + 2);
            }
        }
        __syncthreads();
    }

    // epilogue: +bias, split to hi/lo, store head-major [(b*H+h)][l][d]
    const int row0 = m0 + r0 + (lane >> 2);
    const int row1 = row0 + 8;
    const int bb0 = row0 >> 12, l0r = row0 & (L_ - 1);
    const int bb1 = row1 >> 12, l1r = row1 & (L_ - 1);
#pragma unroll
    for (int nb = 0; nb < 16; nb++) {
        int col = nb * 8 + (lane & 3) * 2;
        int n = n0 + col;
        int hh = n >> 6, d = n & 63;
        float b0 = sbias[col], b1 = sbias[col + 1];
        float v00 = S[nb][0] + b0, v01 = S[nb][1] + b1;
        float v10 = S[nb][2] + b0, v11 = S[nb][3] + b1;
        uint32_t hi0, lo0, hi1, lo1;
        split2(v00, v01, hi0, lo0);
        split2(v10, v11, hi1, lo1);
        size_t off0 = (((size_t)(bb0 * H_ + hh)) * L_ + l0r) * 64 + d;
        size_t off1 = (((size_t)(bb1 * H_ + hh)) * L_ + l1r) * 64 + d;
        *(uint32_t*)&Ohi[off0] = hi0; *(uint32_t*)&Olo[off0] = lo0;
        *(uint32_t*)&Ohi[off1] = hi1; *(uint32_t*)&Olo[off1] = lo1;
    }
}

// ---------------------------------------------------------------------------
// HMMA attention: per CTA one (b,h,128 q-rows), sweep 32 k-tiles of 128.
// ---------------------------------------------------------------------------
#define SM_QHI  0
#define SM_QLO  TILE_B
#define SM_KV0  (2 * TILE_B)             // buf0: Khi,Klo,Vhi,Vlo
#define SM_KV1  (6 * TILE_B)             // buf1
#define SM_RINV (10 * TILE_B)            // float rowinv[128]
#define ATTN_SMEM_BYTES (SM_RINV + 512)

__device__ __forceinline__ void prefetch_tile(uint32_t kv, int bh_in, int kt, int tid)
{
    const char* kh = (const char*)(g_Khi + ((size_t)bh_in * L_ + (size_t)kt * 128) * 64);
    const char* kl = (const char*)(g_Klo + ((size_t)bh_in * L_ + (size_t)kt * 128) * 64);
    const char* vh = (const char*)(g_Vhi + ((size_t)bh_in * L_ + (size_t)kt * 128) * 64);
    const char* vl = (const char*)(g_Vlo + ((size_t)bh_in * L_ + (size_t)kt * 128) * 64);
#pragma unroll
    for (int t = 0; t < 4; t++) {
        int i = tid + t * 256;               // 1024 16B chunks per tensor
        int row = i >> 3, c8 = i & 7;
        uint32_t so = (uint32_t)(row * PITCH + c8 * 8) * 2;
        size_t  go = (size_t)row * 128 + c8 * 16;
        cp16(kv + 0 * TILE_B + so, kh + go);
        cp16(kv + 1 * TILE_B + so, kl + go);
        cp16(kv + 2 * TILE_B + so, vh + go);
        cp16(kv + 3 * TILE_B + so, vl + go);
    }
}

__global__ __launch_bounds__(256) void attn_kernel(float* __restrict__ attn_out)
{
    extern __shared__ __align__(128) char smem[];
    const uint32_t sb = smem_u32(smem);
    float* rowinv = (float*)(smem + SM_RINV);

    const int qt = blockIdx.x, h = blockIdx.y, b = blockIdx.z;
    const int bh_in  = b * H_ + h;
    const int bh_out = h * B_ + b;
    const int tid = threadIdx.x, wid = tid >> 5, lane = tid & 31;
    const int r0 = wid * 16;

    // ---- load Q tile (plain) ----
    {
        const char* qh = (const char*)(g_Qhi + ((size_t)bh_in * L_ + (size_t)qt * 128) * 64);
        const char* ql = (const char*)(g_Qlo + ((size_t)bh_in * L_ + (size_t)qt * 128) * 64);
#pragma unroll
        for (int t = 0; t < 4; t++) {
            int i = tid + t * 256;
            int row = i >> 3, c8 = i & 7;
            uint32_t so = (uint32_t)(row * PITCH + c8 * 8) * 2;
            size_t  go = (size_t)row * 128 + c8 * 16;
            *(uint4*)(smem + SM_QHI + so) = *(const uint4*)(qh + go);
            *(uint4*)(smem + SM_QLO + so) = *(const uint4*)(ql + go);
        }
    }

    // ---- lane-invariant ldmatrix address offsets ----
    const int l7 = lane & 7;
    const uint32_t a_off = (uint32_t)((r0 + l7 + ((lane & 8) ? 8 : 0)) * PITCH
                                      + ((lane & 16) ? 8 : 0)) * 2;
    const uint32_t bk_off = (uint32_t)((l7 + ((lane & 16) ? 8 : 0)) * PITCH
                                       + ((lane & 8) ? 8 : 0)) * 2;
    const uint32_t bv_off = (uint32_t)((l7 + ((lane & 8) ? 8 : 0)) * PITCH
                                       + ((lane & 16) ? 8 : 0)) * 2;

    float* attn_base = attn_out + ((size_t)bh_out * L_ + (size_t)qt * 128) * L_;

    float Oa[8][4];
#pragma unroll
    for (int i = 0; i < 8; i++)
#pragma unroll
        for (int j = 0; j < 4; j++) Oa[i][j] = 0.f;
    float rs0 = 0.f, rs1 = 0.f;

    prefetch_tile(sb + SM_KV0, bh_in, 0, tid);
    CP_COMMIT();

    for (int kt = 0; kt < 32; kt++) {
        const uint32_t kv = sb + ((kt & 1) ? SM_KV1 : SM_KV0);
        if (kt < 31) {
            prefetch_tile(sb + (((kt + 1) & 1) ? SM_KV1 : SM_KV0), bh_in, kt + 1, tid);
            CP_COMMIT();
            CP_WAIT(1);
        } else {
            CP_WAIT(0);
        }
        __syncthreads();   // tile kt visible to all warps

        // ---- GEMM1: S[16x128] = Q @ K^T, 3-way fp16 split ----
        float S[16][4];
#pragma unroll
        for (int i = 0; i < 16; i++)
#pragma unroll
            for (int j = 0; j < 4; j++) S[i][j] = 0.f;

#pragma unroll
        for (int ks = 0; ks < 4; ks++) {
            const uint32_t kc2 = (uint32_t)(ks * 16) * 2;
            uint32_t ah[4], al[4];
            ldm4(ah, sb + SM_QHI + a_off + kc2);
            ldm4(al, sb + SM_QLO + a_off + kc2);
#pragma unroll
            for (int np = 0; np < 8; np++) {
                uint32_t bh4[4], bl4[4];
                uint32_t boff = bk_off + (uint32_t)(np * 16 * PITCH) * 2 + kc2;
                ldm4(bh4, kv + 0 * TILE_B + boff);
                ldm4(bl4, kv + 1 * TILE_B + boff);
                mma16(S[2 * np],     ah, bh4 + 0);
                mma16(S[2 * np],     ah, bl4 + 0);
                mma16(S[2 * np],     al, bh4 + 0);
                mma16(S[2 * np + 1], ah, bh4 + 2);
                mma16(S[2 * np + 1], ah, bl4 + 2);
                mma16(S[2 * np + 1], al, bh4 + 2);
            }
        }

        // ---- epilogue: exp, store E (fp32), rowsum; scale E for fp16 GEMM2 ----
        float* gp0 = attn_base + (size_t)(r0 + (lane >> 2)) * L_ + kt * 128 + (lane & 3) * 2;
        float* gp1 = gp0 + 8 * L_;
        float sum0 = 0.f, sum1 = 0.f;
#pragma unroll
        for (int nb = 0; nb < 16; nb++) {
            float e0 = __expf(S[nb][0] * 0.125f);
            float e1 = __expf(S[nb][1] * 0.125f);
            float e2 = __expf(S[nb][2] * 0.125f);
            float e3 = __expf(S[nb][3] * 0.125f);
            sum0 += e0 + e1; sum1 += e2 + e3;
            *(float2*)(gp0 + nb * 8) = make_float2(e0, e1);
            *(float2*)(gp1 + nb * 8) = make_float2(e2, e3);
            S[nb][0] = e0 * ESCALE; S[nb][1] = e1 * ESCALE;   // keep fp16 in range
            S[nb][2] = e2 * ESCALE; S[nb][3] = e3 * ESCALE;
        }
        sum0 += __shfl_xor_sync(0xFFFFFFFF, sum0, 1);
        sum0 += __shfl_xor_sync(0xFFFFFFFF, sum0, 2);
        sum1 += __shfl_xor_sync(0xFFFFFFFF, sum1, 1);
        sum1 += __shfl_xor_sync(0xFFFFFFFF, sum1, 2);
        rs0 += sum0; rs1 += sum1;

        // ---- GEMM2: O[16x64] += E @ V, 3-way fp16 split, A from registers ----
#pragma unroll
        for (int g = 0; g < 8; g++) {
            uint32_t ah[4], al[4];
            split2(S[2 * g][0],     S[2 * g][1],     ah[0], al[0]);
            split2(S[2 * g][2],     S[2 * g][3],     ah[1], al[1]);
            split2(S[2 * g + 1][0], S[2 * g + 1][1], ah[2], al[2]);
            split2(S[2 * g + 1][2], S[2 * g + 1][3], ah[3], al[3]);
            uint32_t vbase = bv_off + (uint32_t)(g * 16 * PITCH) * 2;
#pragma unroll
            for (int np = 0; np < 4; np++) {
                uint32_t vh4[4], vl4[4];
                uint32_t voff = vbase + (uint32_t)(np * 16) * 2;
                ldm4t(vh4, kv + 2 * TILE_B + voff);
                ldm4t(vl4, kv + 3 * TILE_B + voff);
                mma16(Oa[2 * np],     ah, vh4 + 0);
                mma16(Oa[2 * np],     ah, vl4 + 0);
                mma16(Oa[2 * np],     al, vh4 + 0);
                mma16(Oa[2 * np + 1], ah, vh4 + 2);
                mma16(Oa[2 * np + 1], ah, vl4 + 2);
                mma16(Oa[2 * np + 1], al, vh4 + 2);
            }
        }
        __syncthreads();   // all warps done reading buf before it is refilled
    }

    // ---- rowsums + reciprocals (x64 undoes the E pre-scale) ----
    if ((lane & 3) == 0) {
        int rr = r0 + (lane >> 2);
        g_rowsum[(size_t)bh_out * L_ + (size_t)qt * 128 + rr]     = rs0;
        g_rowsum[(size_t)bh_out * L_ + (size_t)qt * 128 + rr + 8] = rs1;
        rowinv[rr]     = EUNSCALE / rs0;
        rowinv[rr + 8] = EUNSCALE / rs1;
    }
    __syncthreads();

    // ---- normalize O and store ----
    {
        float i0 = rowinv[r0 + (lane >> 2)];
        float i1 = rowinv[r0 + (lane >> 2) + 8];
        float* op0 = g_O + ((size_t)bh_in * L_ + (size_t)qt * 128 + r0 + (lane >> 2)) * 64;
        float* op1 = op0 + 8 * 64;
#pragma unroll
        for (int nb = 0; nb < 8; nb++) {
            int col = nb * 8 + (lane & 3) * 2;
            *(float2*)(op0 + col) = make_float2(Oa[nb][0] * i0, Oa[nb][1] * i0);
            *(float2*)(op1 + col) = make_float2(Oa[nb][2] * i1, Oa[nb][3] * i1);
        }
    }
}

// ---------------------------------------------------------------------------
// Reciprocal of rowsums
// ---------------------------------------------------------------------------
__global__ void recip_kernel()
{
    int i = blockIdx.x * blockDim.x + threadIdx.x;
    if (i < BH_ * L_) g_rowsum[i] = 1.0f / g_rowsum[i];
}

// ---------------------------------------------------------------------------
// Normalize attn in place:  attn[row][*] *= inv_rowsum[row]
// ---------------------------------------------------------------------------
__global__ __launch_bounds__(256) void norm_attn_kernel(float* __restrict__ attn)
{
    int i = blockIdx.x * blockDim.x + threadIdx.x;   // float4 index
    int row = i >> 10;                               // 1024 float4 per row
    float inv = g_rowsum[row];
    float4* p = (float4*)attn + i;
    float4 v = *p;
    v.x *= inv; v.y *= inv; v.z *= inv; v.w *= inv;
    *p = v;
}

// ---------------------------------------------------------------------------
// Final FC: out = ctx @ fc_w.T + fc_b.  M=8192, N=64, K=512.
// ---------------------------------------------------------------------------
__global__ __launch_bounds__(256) void fc_kernel(
    const float* __restrict__ fc_w, const float* __restrict__ fc_b,
    float* __restrict__ out)
{
    __shared__ float As[8][132];
    __shared__ float Bs[8][68];

    const int m0 = blockIdx.x * 128;
    const int tid = threadIdx.x;
    const int warp = tid >> 5, lane = tid & 31;
    const int wm = warp & 3, wn = warp >> 2;
    const int rm = wm * 32 + (lane & 3) * 4;
    const int cn = wn * 32 + (lane >> 2) * 4;

    float acc[8][4];
#pragma unroll
    for (int i = 0; i < 8; i++)
#pragma unroll
        for (int j = 0; j < 4; j++) acc[i][j] = 0.f;

    const int lrow = tid >> 1;
    const int lkq  = (tid & 1) * 4;

    for (int k0 = 0; k0 < 512; k0 += 8) {
        {
            int m = m0 + lrow;
            int bb = m >> 12, l = m & (L_ - 1);
            int k = k0 + lkq;
            int hh = k >> 6, d = k & 63;
            float4 v = *(const float4*)&g_O[(((size_t)(bb * H_ + hh)) * L_ + l) * 64 + d];
            As[lkq + 0][lrow] = v.x; As[lkq + 1][lrow] = v.y;
            As[lkq + 2][lrow] = v.z; As[lkq + 3][lrow] = v.w;
        }
        if (tid < 128) {
            int n = tid >> 1;
            int kq = (tid & 1) * 4;
            float4 w = *(const float4*)&fc_w[(size_t)n * 512 + k0 + kq];
            Bs[kq + 0][n] = w.x; Bs[kq + 1][n] = w.y;
            Bs[kq + 2][n] = w.z; Bs[kq + 3][n] = w.w;
        }
        __syncthreads();
#pragma unroll
        for (int kk = 0; kk < 8; kk++) {
            float a[8], bv[4];
            *(float4*)&a[0] = *(const float4*)&As[kk][rm];
            *(float4*)&a[4] = *(const float4*)&As[kk][rm + 16];
            *(float4*)&bv[0] = *(const float4*)&Bs[kk][cn];
#pragma unroll
            for (int i = 0; i < 8; i++)
#pragma unroll
                for (int j = 0; j < 4; j++) acc[i][j] += a[i] * bv[j];
        }
        __syncthreads();
    }

#pragma unroll
    for (int i = 0; i < 8; i++) {
        int m = m0 + rm + ((i < 4) ? i : 12 + i);
#pragma unroll
        for (int j = 0; j < 4; j++) {
            out[(size_t)m * 64 + cn + j] = acc[i][j] + fc_b[cn + j];
        }
    }
}

// ---------------------------------------------------------------------------
// Launch
// ---------------------------------------------------------------------------
extern "C" void kernel_launch(void* const* d_in, const int* in_sizes, int n_in,
                              void* d_out, int out_size)
{
    const float* q    = (const float*)d_in[0];
    const float* k    = (const float*)d_in[1];
    const float* v    = (const float*)d_in[2];
    const float* wq   = (const float*)d_in[3];
    const float* bq   = (const float*)d_in[4];
    const float* wk   = (const float*)d_in[5];
    const float* bk   = (const float*)d_in[6];
    const float* wv   = (const float*)d_in[7];
    const float* bv   = (const float*)d_in[8];
    const float* fc_w = (const float*)d_in[9];
    const float* fc_b = (const float*)d_in[10];

    float* out  = (float*)d_out;                        // [B, L, DV]
    float* attn = out + (size_t)B_ * L_ * 64;           // [H*B, L, L]

    cudaFuncSetAttribute(attn_kernel,
                         cudaFuncAttributeMaxDynamicSharedMemorySize,
                         ATTN_SMEM_BYTES);
    cudaFuncSetAttribute(proj_mma,
                         cudaFuncAttributeMaxDynamicSharedMemorySize,
                         PROJ_SMEM);

    // get device pointers to static scratch (host cannot take address directly)
    __half *xhi, *xlo, *whi, *wlo;
    cudaGetSymbolAddress((void**)&xhi, g_Xhi);
    cudaGetSymbolAddress((void**)&xlo, g_Xlo);
    cudaGetSymbolAddress((void**)&whi, g_Whi);
    cudaGetSymbolAddress((void**)&wlo, g_Wlo);

    const int NX = B_ * L_ * D_;         // 4,194,304
    const int NW = D_ * D_;              // 262,144
    split_kernel<<<NX / 4 / 256, 256>>>(q, xhi + 0 * (size_t)NX, xlo + 0 * (size_t)NX, NX / 4);
    split_kernel<<<NX / 4 / 256, 256>>>(k, xhi + 1 * (size_t)NX, xlo + 1 * (size_t)NX, NX / 4);
    split_kernel<<<NX / 4 / 256, 256>>>(v, xhi + 2 * (size_t)NX, xlo + 2 * (size_t)NX, NX / 4);
    split_kernel<<<NW / 4 / 256, 256>>>(wq, whi + 0 * (size_t)NW, wlo + 0 * (size_t)NW, NW / 4);
    split_kernel<<<NW / 4 / 256, 256>>>(wk, whi + 1 * (size_t)NW, wlo + 1 * (size_t)NW, NW / 4);
    split_kernel<<<NW / 4 / 256, 256>>>(wv, whi + 2 * (size_t)NW, wlo + 2 * (size_t)NW, NW / 4);

    dim3 pg(4, 64);
    proj_mma<<<pg, 256, PROJ_SMEM>>>(bq, 0);
    proj_mma<<<pg, 256, PROJ_SMEM>>>(bk, 1);
    proj_mma<<<pg, 256, PROJ_SMEM>>>(bv, 2);

    dim3 ag(L_ / 128, H_, B_);
    attn_kernel<<<ag, 256, ATTN_SMEM_BYTES>>>(attn);

    recip_kernel<<<(BH_ * L_ + 255) / 256, 256>>>();

    int n4 = BH_ * L_ * (L_ / 4);
    norm_attn_kernel<<<n4 / 256, 256>>>(attn);

    fc_kernel<<<(B_ * L_) / 128, 256>>>(fc_w, fc_b, out);

    (void)in_sizes; (void)n_in; (void)out_size;
}

// round 15
// speedup vs baseline: 1.0532x; 1.0532x over previous
#include <cuda_runtime.h>
#include <cuda_fp16.h>
#include <cstdint>

// Problem constants
#define B_ 2
#define L_ 4096
#define D_ 512
#define H_ 8
#define BH_ (B_ * H_)

// E is scaled by 2^-6 before fp16 conversion (exp(S/8) can reach ~7e4 > fp16 max);
// the x64 is folded back into the O normalization.
#define ESCALE 0.015625f
#define EUNSCALE 64.0f

// ---------------------------------------------------------------------------
// Static device scratch (allocation-free).
// ---------------------------------------------------------------------------
__device__ __half g_Qhi[BH_ * L_ * 64];
__device__ __half g_Qlo[BH_ * L_ * 64];
__device__ __half g_Khi[BH_ * L_ * 64];
__device__ __half g_Klo[BH_ * L_ * 64];
__device__ __half g_Vhi[BH_ * L_ * 64];
__device__ __half g_Vlo[BH_ * L_ * 64];
__device__ __half g_Xhi[3][B_ * L_ * D_];   // fp16 hi/lo splits of inputs q,k,v
__device__ __half g_Xlo[3][B_ * L_ * D_];
__device__ __half g_Whi[3][D_ * D_];        // splits of wq,wk,wv
__device__ __half g_Wlo[3][D_ * D_];
__device__ float  g_O[BH_ * L_ * 64];       // normalized context [b][h][l][dv]
__device__ float  g_rowsum[BH_ * L_];       // softmax denominators [(h*B+b)][l]

// ---------------------------------------------------------------------------
// mma.sync / ldmatrix / cp.async helpers (base sm_103 features, no 'a')
// ---------------------------------------------------------------------------
__device__ __forceinline__ uint32_t smem_u32(const void* p) {
    uint32_t a;
    asm("{ .reg .u64 t; cvta.to.shared.u64 t, %1; cvt.u32.u64 %0, t; }"
        : "=r"(a) : "l"(p));
    return a;
}
__device__ __forceinline__ void ldm4(uint32_t* r, uint32_t a) {
    asm volatile("ldmatrix.sync.aligned.m8n8.x4.shared.b16 {%0,%1,%2,%3}, [%4];"
        : "=r"(r[0]), "=r"(r[1]), "=r"(r[2]), "=r"(r[3]) : "r"(a));
}
__device__ __forceinline__ void ldm4t(uint32_t* r, uint32_t a) {
    asm volatile("ldmatrix.sync.aligned.m8n8.x4.trans.shared.b16 {%0,%1,%2,%3}, [%4];"
        : "=r"(r[0]), "=r"(r[1]), "=r"(r[2]), "=r"(r[3]) : "r"(a));
}
__device__ __forceinline__ void mma16(float* d, const uint32_t* a, const uint32_t* b) {
    asm volatile("mma.sync.aligned.m16n8k16.row.col.f32.f16.f16.f32 "
        "{%0,%1,%2,%3}, {%4,%5,%6,%7}, {%8,%9}, {%0,%1,%2,%3};"
        : "+f"(d[0]), "+f"(d[1]), "+f"(d[2]), "+f"(d[3])
        : "r"(a[0]), "r"(a[1]), "r"(a[2]), "r"(a[3]), "r"(b[0]), "r"(b[1]));
}
__device__ __forceinline__ void cp16(uint32_t s, const void* g) {
    asm volatile("cp.async.cg.shared.global [%0], [%1], 16;" :: "r"(s), "l"(g) : "memory");
}
#define CP_COMMIT()  asm volatile("cp.async.commit_group;" ::: "memory")
#define CP_WAIT(n)   asm volatile("cp.async.wait_group %0;" :: "n"(n) : "memory")

// split a float pair into fp16 hi / lo packed b32 regs
__device__ __forceinline__ void split2(float a, float b, uint32_t& hi, uint32_t& lo) {
    __half ha = __float2half_rn(a), hb = __float2half_rn(b);
    __half la = __float2half_rn(a - __half2float(ha));
    __half lb = __float2half_rn(b - __half2float(hb));
    __half2 h = __halves2half2(ha, hb), l = __halves2half2(la, lb);
    hi = *(uint32_t*)&h; lo = *(uint32_t*)&l;
}
// pack a float pair to fp16x2 (single cvt)
__device__ __forceinline__ uint32_t pack2(float a, float b) {
    __half2 h = __floats2half2_rn(a, b);
    return *(uint32_t*)&h;
}

#define PITCH 72                         // halfs per smem row (144B, 16B-mult)
#define TILE_B (128 * PITCH * 2)         // 18432 bytes per 128x64 fp16 tile

// ---------------------------------------------------------------------------
// split_kernel: fp32 -> fp16 hi/lo (grid-stride over float4)
// ---------------------------------------------------------------------------
__global__ __launch_bounds__(256) void split_kernel(
    const float* __restrict__ src, __half* __restrict__ hi,
    __half* __restrict__ lo, int n4)
{
    int i = blockIdx.x * blockDim.x + threadIdx.x;
    if (i >= n4) return;
    float4 v = ((const float4*)src)[i];
    __half h0 = __float2half_rn(v.x), h1 = __float2half_rn(v.y);
    __half h2 = __float2half_rn(v.z), h3 = __float2half_rn(v.w);
    __half l0 = __float2half_rn(v.x - __half2float(h0));
    __half l1 = __float2half_rn(v.y - __half2float(h1));
    __half l2 = __float2half_rn(v.z - __half2float(h2));
    __half l3 = __float2half_rn(v.w - __half2float(h3));
    __half2* hp = (__half2*)&hi[4 * (size_t)i];
    __half2* lp = (__half2*)&lo[4 * (size_t)i];
    hp[0] = __halves2half2(h0, h1); hp[1] = __halves2half2(h2, h3);
    lp[0] = __halves2half2(l0, l1); lp[1] = __halves2half2(l2, l3);
}

// ---------------------------------------------------------------------------
// proj_mma: C = X @ W.T + bias -> fp16 hi/lo splits in head-major layout.
// M=8192, N=512, K=512.  CTA: 128x128, 8 warps (16 rows x 128 cols each).
// ---------------------------------------------------------------------------
#define PROJ_SMEM (8 * TILE_B + 512)

__global__ __launch_bounds__(256) void proj_mma(const float* __restrict__ bias, int sel)
{
    extern __shared__ __align__(128) char smem[];
    const uint32_t sb = smem_u32(smem);
    float* sbias = (float*)(smem + 8 * TILE_B);

    const __half* Xhi = g_Xhi[sel];
    const __half* Xlo = g_Xlo[sel];
    const __half* Whi = g_Whi[sel];
    const __half* Wlo = g_Wlo[sel];
    __half* Ohi = (sel == 0) ? g_Qhi : (sel == 1) ? g_Khi : g_Vhi;
    __half* Olo = (sel == 0) ? g_Qlo : (sel == 1) ? g_Klo : g_Vlo;

    const int n0 = blockIdx.x * 128;
    const int m0 = blockIdx.y * 128;
    const int tid = threadIdx.x, wid = tid >> 5, lane = tid & 31;
    const int r0 = wid * 16;

    if (tid < 128) sbias[tid] = bias[n0 + tid];

    const int l7 = lane & 7;
    const uint32_t a_off = (uint32_t)((r0 + l7 + ((lane & 8) ? 8 : 0)) * PITCH
                                      + ((lane & 16) ? 8 : 0)) * 2;
    const uint32_t bk_off = (uint32_t)((l7 + ((lane & 16) ? 8 : 0)) * PITCH
                                       + ((lane & 8) ? 8 : 0)) * 2;

    float S[16][4];
#pragma unroll
    for (int i = 0; i < 16; i++)
#pragma unroll
        for (int j = 0; j < 4; j++) S[i][j] = 0.f;

    auto prefetch = [&](int kc, uint32_t buf) {
#pragma unroll
        for (int t = 0; t < 4; t++) {
            int i = tid + t * 256;
            int row = i >> 3, c8 = i & 7;
            uint32_t so = (uint32_t)(row * PITCH + c8 * 8) * 2;
            size_t xg = ((size_t)(m0 + row) * 512 + kc * 64 + c8 * 8) * 2;
            size_t wg = ((size_t)(n0 + row) * 512 + kc * 64 + c8 * 8) * 2;
            cp16(buf + 0 * TILE_B + so, (const char*)Xhi + xg);
            cp16(buf + 1 * TILE_B + so, (const char*)Xlo + xg);
            cp16(buf + 2 * TILE_B + so, (const char*)Whi + wg);
            cp16(buf + 3 * TILE_B + so, (const char*)Wlo + wg);
        }
    };

    prefetch(0, sb);
    CP_COMMIT();

    for (int kc = 0; kc < 8; kc++) {
        const uint32_t buf = sb + ((kc & 1) ? 4 * TILE_B : 0);
        if (kc < 7) {
            prefetch(kc + 1, sb + (((kc + 1) & 1) ? 4 * TILE_B : 0));
            CP_COMMIT();
            CP_WAIT(1);
        } else {
            CP_WAIT(0);
        }
        __syncthreads();

#pragma unroll
        for (int ks = 0; ks < 4; ks++) {
            const uint32_t kc2 = (uint32_t)(ks * 16) * 2;
            uint32_t ah[4], al[4];
            ldm4(ah, buf + 0 * TILE_B + a_off + kc2);
            ldm4(al, buf + 1 * TILE_B + a_off + kc2);
#pragma unroll
            for (int np = 0; np < 8; np++) {
                uint32_t bh4[4], bl4[4];
                uint32_t boff = bk_off + (uint32_t)(np * 16 * PITCH) * 2 + kc2;
                ldm4(bh4, buf + 2 * TILE_B + boff);
                ldm4(bl4, buf + 3 * TILE_B + boff);
                mma16(S[2 * np],     ah, bh4 + 0);
                mma16(S[2 * np],     ah, bl4 + 0);
                mma16(S[2 * np],     al, bh4 + 0);
                mma16(S[2 * np + 1], ah, bh4 + 2);
                mma16(S[2 * np + 1], ah, bl4 + 2);
                mma16(S[2 * np + 1], al, bh4 + 2);
            }
        }
        __syncthreads();
    }

    const int row0 = m0 + r0 + (lane >> 2);
    const int row1 = row0 + 8;
    const int bb0 = row0 >> 12, l0r = row0 & (L_ - 1);
    const int bb1 = row1 >> 12, l1r = row1 & (L_ - 1);
#pragma unroll
    for (int nb = 0; nb < 16; nb++) {
        int col = nb * 8 + (lane & 3) * 2;
        int n = n0 + col;
        int hh = n >> 6, d = n & 63;
        float b0 = sbias[col], b1 = sbias[col + 1];
        float v00 = S[nb][0] + b0, v01 = S[nb][1] + b1;
        float v10 = S[nb][2] + b0, v11 = S[nb][3] + b1;
        uint32_t hi0, lo0, hi1, lo1;
        split2(v00, v01, hi0, lo0);
        split2(v10, v11, hi1, lo1);
        size_t off0 = (((size_t)(bb0 * H_ + hh)) * L_ + l0r) * 64 + d;
        size_t off1 = (((size_t)(bb1 * H_ + hh)) * L_ + l1r) * 64 + d;
        *(uint32_t*)&Ohi[off0] = hi0; *(uint32_t*)&Olo[off0] = lo0;
        *(uint32_t*)&Ohi[off1] = hi1; *(uint32_t*)&Olo[off1] = lo1;
    }
}

// ---------------------------------------------------------------------------
// HMMA attention: per CTA one (b,h,128 q-rows), sweep 32 k-tiles of 128.
// GEMM1 3-term fp16 split (precision for exp); GEMM2 2-term: Ehi*(Vhi+Vlo)
// (E rounding 2^-12 -> ~2e-4 on out, attn output stays exact fp32 path).
// ---------------------------------------------------------------------------
#define SM_QHI  0
#define SM_QLO  TILE_B
#define SM_KV0  (2 * TILE_B)             // buf0: Khi,Klo,Vhi,Vlo
#define SM_KV1  (6 * TILE_B)             // buf1
#define SM_RINV (10 * TILE_B)            // float rowinv[128]
#define ATTN_SMEM_BYTES (SM_RINV + 512)

__device__ __forceinline__ void prefetch_tile(uint32_t kv, int bh_in, int kt, int tid)
{
    const char* kh = (const char*)(g_Khi + ((size_t)bh_in * L_ + (size_t)kt * 128) * 64);
    const char* kl = (const char*)(g_Klo + ((size_t)bh_in * L_ + (size_t)kt * 128) * 64);
    const char* vh = (const char*)(g_Vhi + ((size_t)bh_in * L_ + (size_t)kt * 128) * 64);
    const char* vl = (const char*)(g_Vlo + ((size_t)bh_in * L_ + (size_t)kt * 128) * 64);
#pragma unroll
    for (int t = 0; t < 4; t++) {
        int i = tid + t * 256;               // 1024 16B chunks per tensor
        int row = i >> 3, c8 = i & 7;
        uint32_t so = (uint32_t)(row * PITCH + c8 * 8) * 2;
        size_t  go = (size_t)row * 128 + c8 * 16;
        cp16(kv + 0 * TILE_B + so, kh + go);
        cp16(kv + 1 * TILE_B + so, kl + go);
        cp16(kv + 2 * TILE_B + so, vh + go);
        cp16(kv + 3 * TILE_B + so, vl + go);
    }
}

__global__ __launch_bounds__(256) void attn_kernel(float* __restrict__ attn_out)
{
    extern __shared__ __align__(128) char smem[];
    const uint32_t sb = smem_u32(smem);
    float* rowinv = (float*)(smem + SM_RINV);

    const int qt = blockIdx.x, h = blockIdx.y, b = blockIdx.z;
    const int bh_in  = b * H_ + h;
    const int bh_out = h * B_ + b;
    const int tid = threadIdx.x, wid = tid >> 5, lane = tid & 31;
    const int r0 = wid * 16;

    // ---- load Q tile (plain) ----
    {
        const char* qh = (const char*)(g_Qhi + ((size_t)bh_in * L_ + (size_t)qt * 128) * 64);
        const char* ql = (const char*)(g_Qlo + ((size_t)bh_in * L_ + (size_t)qt * 128) * 64);
#pragma unroll
        for (int t = 0; t < 4; t++) {
            int i = tid + t * 256;
            int row = i >> 3, c8 = i & 7;
            uint32_t so = (uint32_t)(row * PITCH + c8 * 8) * 2;
            size_t  go = (size_t)row * 128 + c8 * 16;
            *(uint4*)(smem + SM_QHI + so) = *(const uint4*)(qh + go);
            *(uint4*)(smem + SM_QLO + so) = *(const uint4*)(ql + go);
        }
    }

    // ---- lane-invariant ldmatrix address offsets ----
    const int l7 = lane & 7;
    const uint32_t a_off = (uint32_t)((r0 + l7 + ((lane & 8) ? 8 : 0)) * PITCH
                                      + ((lane & 16) ? 8 : 0)) * 2;
    const uint32_t bk_off = (uint32_t)((l7 + ((lane & 16) ? 8 : 0)) * PITCH
                                       + ((lane & 8) ? 8 : 0)) * 2;
    const uint32_t bv_off = (uint32_t)((l7 + ((lane & 8) ? 8 : 0)) * PITCH
                                       + ((lane & 16) ? 8 : 0)) * 2;

    float* attn_base = attn_out + ((size_t)bh_out * L_ + (size_t)qt * 128) * L_;

    float Oa[8][4];
#pragma unroll
    for (int i = 0; i < 8; i++)
#pragma unroll
        for (int j = 0; j < 4; j++) Oa[i][j] = 0.f;
    float rs0 = 0.f, rs1 = 0.f;

    prefetch_tile(sb + SM_KV0, bh_in, 0, tid);
    CP_COMMIT();

    for (int kt = 0; kt < 32; kt++) {
        const uint32_t kv = sb + ((kt & 1) ? SM_KV1 : SM_KV0);
        if (kt < 31) {
            prefetch_tile(sb + (((kt + 1) & 1) ? SM_KV1 : SM_KV0), bh_in, kt + 1, tid);
            CP_COMMIT();
            CP_WAIT(1);
        } else {
            CP_WAIT(0);
        }
        __syncthreads();   // tile kt visible to all warps

        // ---- GEMM1: S[16x128] = Q @ K^T, 3-way fp16 split ----
        float S[16][4];
#pragma unroll
        for (int i = 0; i < 16; i++)
#pragma unroll
            for (int j = 0; j < 4; j++) S[i][j] = 0.f;

#pragma unroll
        for (int ks = 0; ks < 4; ks++) {
            const uint32_t kc2 = (uint32_t)(ks * 16) * 2;
            uint32_t ah[4], al[4];
            ldm4(ah, sb + SM_QHI + a_off + kc2);
            ldm4(al, sb + SM_QLO + a_off + kc2);
#pragma unroll
            for (int np = 0; np < 8; np++) {
                uint32_t bh4[4], bl4[4];
                uint32_t boff = bk_off + (uint32_t)(np * 16 * PITCH) * 2 + kc2;
                ldm4(bh4, kv + 0 * TILE_B + boff);
                ldm4(bl4, kv + 1 * TILE_B + boff);
                mma16(S[2 * np],     ah, bh4 + 0);
                mma16(S[2 * np],     ah, bl4 + 0);
                mma16(S[2 * np],     al, bh4 + 0);
                mma16(S[2 * np + 1], ah, bh4 + 2);
                mma16(S[2 * np + 1], ah, bl4 + 2);
                mma16(S[2 * np + 1], al, bh4 + 2);
            }
        }

        // ---- epilogue: exp, store E (fp32), rowsum; scale E for fp16 GEMM2 ----
        float* gp0 = attn_base + (size_t)(r0 + (lane >> 2)) * L_ + kt * 128 + (lane & 3) * 2;
        float* gp1 = gp0 + 8 * L_;
        float sum0 = 0.f, sum1 = 0.f;
#pragma unroll
        for (int nb = 0; nb < 16; nb++) {
            float e0 = __expf(S[nb][0] * 0.125f);
            float e1 = __expf(S[nb][1] * 0.125f);
            float e2 = __expf(S[nb][2] * 0.125f);
            float e3 = __expf(S[nb][3] * 0.125f);
            sum0 += e0 + e1; sum1 += e2 + e3;
            *(float2*)(gp0 + nb * 8) = make_float2(e0, e1);
            *(float2*)(gp1 + nb * 8) = make_float2(e2, e3);
            S[nb][0] = e0 * ESCALE; S[nb][1] = e1 * ESCALE;   // keep fp16 in range
            S[nb][2] = e2 * ESCALE; S[nb][3] = e3 * ESCALE;
        }
        sum0 += __shfl_xor_sync(0xFFFFFFFF, sum0, 1);
        sum0 += __shfl_xor_sync(0xFFFFFFFF, sum0, 2);
        sum1 += __shfl_xor_sync(0xFFFFFFFF, sum1, 1);
        sum1 += __shfl_xor_sync(0xFFFFFFFF, sum1, 2);
        rs0 += sum0; rs1 += sum1;

        // ---- GEMM2: O[16x64] += Ehi @ (Vhi + Vlo), A packed from registers ----
#pragma unroll
        for (int g = 0; g < 8; g++) {
            uint32_t ah[4];
            ah[0] = pack2(S[2 * g][0],     S[2 * g][1]);
            ah[1] = pack2(S[2 * g][2],     S[2 * g][3]);
            ah[2] = pack2(S[2 * g + 1][0], S[2 * g + 1][1]);
            ah[3] = pack2(S[2 * g + 1][2], S[2 * g + 1][3]);
            uint32_t vbase = bv_off + (uint32_t)(g * 16 * PITCH) * 2;
#pragma unroll
            for (int np = 0; np < 4; np++) {
                uint32_t vh4[4], vl4[4];
                uint32_t voff = vbase + (uint32_t)(np * 16) * 2;
                ldm4t(vh4, kv + 2 * TILE_B + voff);
                ldm4t(vl4, kv + 3 * TILE_B + voff);
                mma16(Oa[2 * np],     ah, vh4 + 0);
                mma16(Oa[2 * np],     ah, vl4 + 0);
                mma16(Oa[2 * np + 1], ah, vh4 + 2);
                mma16(Oa[2 * np + 1], ah, vl4 + 2);
            }
        }
        __syncthreads();   // all warps done reading buf before it is refilled
    }

    // ---- rowsums + reciprocals (x64 undoes the E pre-scale) ----
    if ((lane & 3) == 0) {
        int rr = r0 + (lane >> 2);
        g_rowsum[(size_t)bh_out * L_ + (size_t)qt * 128 + rr]     = rs0;
        g_rowsum[(size_t)bh_out * L_ + (size_t)qt * 128 + rr + 8] = rs1;
        rowinv[rr]     = EUNSCALE / rs0;
        rowinv[rr + 8] = EUNSCALE / rs1;
    }
    __syncthreads();

    // ---- normalize O and store ----
    {
        float i0 = rowinv[r0 + (lane >> 2)];
        float i1 = rowinv[r0 + (lane >> 2) + 8];
        float* op0 = g_O + ((size_t)bh_in * L_ + (size_t)qt * 128 + r0 + (lane >> 2)) * 64;
        float* op1 = op0 + 8 * 64;
#pragma unroll
        for (int nb = 0; nb < 8; nb++) {
            int col = nb * 8 + (lane & 3) * 2;
            *(float2*)(op0 + col) = make_float2(Oa[nb][0] * i0, Oa[nb][1] * i0);
            *(float2*)(op1 + col) = make_float2(Oa[nb][2] * i1, Oa[nb][3] * i1);
        }
    }
}

// ---------------------------------------------------------------------------
// Reciprocal of rowsums
// ---------------------------------------------------------------------------
__global__ void recip_kernel()
{
    int i = blockIdx.x * blockDim.x + threadIdx.x;
    if (i < BH_ * L_) g_rowsum[i] = 1.0f / g_rowsum[i];
}

// ---------------------------------------------------------------------------
// Normalize attn in place:  attn[row][*] *= inv_rowsum[row]
// ---------------------------------------------------------------------------
__global__ __launch_bounds__(256) void norm_attn_kernel(float* __restrict__ attn)
{
    int i = blockIdx.x * blockDim.x + threadIdx.x;   // float4 index
    int row = i >> 10;                               // 1024 float4 per row
    float inv = g_rowsum[row];
    float4* p = (float4*)attn + i;
    float4 v = *p;
    v.x *= inv; v.y *= inv; v.z *= inv; v.w *= inv;
    *p = v;
}

// ---------------------------------------------------------------------------
// Final FC: out = ctx @ fc_w.T + fc_b.  M=8192, N=64, K=512.
// ---------------------------------------------------------------------------
__global__ __launch_bounds__(256) void fc_kernel(
    const float* __restrict__ fc_w, const float* __restrict__ fc_b,
    float* __restrict__ out)
{
    __shared__ float As[8][132];
    __shared__ float Bs[8][68];

    const int m0 = blockIdx.x * 128;
    const int tid = threadIdx.x;
    const int warp = tid >> 5, lane = tid & 31;
    const int wm = warp & 3, wn = warp >> 2;
    const int rm = wm * 32 + (lane & 3) * 4;
    const int cn = wn * 32 + (lane >> 2) * 4;

    float acc[8][4];
#pragma unroll
    for (int i = 0; i < 8; i++)
#pragma unroll
        for (int j = 0; j < 4; j++) acc[i][j] = 0.f;

    const int lrow = tid >> 1;
    const int lkq  = (tid & 1) * 4;

    for (int k0 = 0; k0 < 512; k0 += 8) {
        {
            int m = m0 + lrow;
            int bb = m >> 12, l = m & (L_ - 1);
            int k = k0 + lkq;
            int hh = k >> 6, d = k & 63;
            float4 v = *(const float4*)&g_O[(((size_t)(bb * H_ + hh)) * L_ + l) * 64 + d];
            As[lkq + 0][lrow] = v.x; As[lkq + 1][lrow] = v.y;
            As[lkq + 2][lrow] = v.z; As[lkq + 3][lrow] = v.w;
        }
        if (tid < 128) {
            int n = tid >> 1;
            int kq = (tid & 1) * 4;
            float4 w = *(const float4*)&fc_w[(size_t)n * 512 + k0 + kq];
            Bs[kq + 0][n] = w.x; Bs[kq + 1][n] = w.y;
            Bs[kq + 2][n] = w.z; Bs[kq + 3][n] = w.w;
        }
        __syncthreads();
#pragma unroll
        for (int kk = 0; kk < 8; kk++) {
            float a[8], bv[4];
            *(float4*)&a[0] = *(const float4*)&As[kk][rm];
            *(float4*)&a[4] = *(const float4*)&As[kk][rm + 16];
            *(float4*)&bv[0] = *(const float4*)&Bs[kk][cn];
#pragma unroll
            for (int i = 0; i < 8; i++)
#pragma unroll
                for (int j = 0; j < 4; j++) acc[i][j] += a[i] * bv[j];
        }
        __syncthreads();
    }

#pragma unroll
    for (int i = 0; i < 8; i++) {
        int m = m0 + rm + ((i < 4) ? i : 12 + i);
#pragma unroll
        for (int j = 0; j < 4; j++) {
            out[(size_t)m * 64 + cn + j] = acc[i][j] + fc_b[cn + j];
        }
    }
}

// ---------------------------------------------------------------------------
// Launch
// ---------------------------------------------------------------------------
extern "C" void kernel_launch(void* const* d_in, const int* in_sizes, int n_in,
                              void* d_out, int out_size)
{
    const float* q    = (const float*)d_in[0];
    const float* k    = (const float*)d_in[1];
    const float* v    = (const float*)d_in[2];
    const float* wq   = (const float*)d_in[3];
    const float* bq   = (const float*)d_in[4];
    const float* wk   = (const float*)d_in[5];
    const float* bk   = (const float*)d_in[6];
    const float* wv   = (const float*)d_in[7];
    const float* bv   = (const float*)d_in[8];
    const float* fc_w = (const float*)d_in[9];
    const float* fc_b = (const float*)d_in[10];

    float* out  = (float*)d_out;                        // [B, L, DV]
    float* attn = out + (size_t)B_ * L_ * 64;           // [H*B, L, L]

    cudaFuncSetAttribute(attn_kernel,
                         cudaFuncAttributeMaxDynamicSharedMemorySize,
                         ATTN_SMEM_BYTES);
    cudaFuncSetAttribute(proj_mma,
                         cudaFuncAttributeMaxDynamicSharedMemorySize,
                         PROJ_SMEM);

    __half *xhi, *xlo, *whi, *wlo;
    cudaGetSymbolAddress((void**)&xhi, g_Xhi);
    cudaGetSymbolAddress((void**)&xlo, g_Xlo);
    cudaGetSymbolAddress((void**)&whi, g_Whi);
    cudaGetSymbolAddress((void**)&wlo, g_Wlo);

    const int NX = B_ * L_ * D_;         // 4,194,304
    const int NW = D_ * D_;              // 262,144
    split_kernel<<<NX / 4 / 256, 256>>>(q, xhi + 0 * (size_t)NX, xlo + 0 * (size_t)NX, NX / 4);
    split_kernel<<<NX / 4 / 256, 256>>>(k, xhi + 1 * (size_t)NX, xlo + 1 * (size_t)NX, NX / 4);
    split_kernel<<<NX / 4 / 256, 256>>>(v, xhi + 2 * (size_t)NX, xlo + 2 * (size_t)NX, NX / 4);
    split_kernel<<<NW / 4 / 256, 256>>>(wq, whi + 0 * (size_t)NW, wlo + 0 * (size_t)NW, NW / 4);
    split_kernel<<<NW / 4 / 256, 256>>>(wk, whi + 1 * (size_t)NW, wlo + 1 * (size_t)NW, NW / 4);
    split_kernel<<<NW / 4 / 256, 256>>>(wv, whi + 2 * (size_t)NW, wlo + 2 * (size_t)NW, NW / 4);

    dim3 pg(4, 64);
    proj_mma<<<pg, 256, PROJ_SMEM>>>(bq, 0);
    proj_mma<<<pg, 256, PROJ_SMEM>>>(bk, 1);
    proj_mma<<<pg, 256, PROJ_SMEM>>>(bv, 2);

    dim3 ag(L_ / 128, H_, B_);
    attn_kernel<<<ag, 256, ATTN_SMEM_BYTES>>>(attn);

    recip_kernel<<<(BH_ * L_ + 255) / 256, 256>>>();

    int n4 = BH_ * L_ * (L_ / 4);
    norm_attn_kernel<<<n4 / 256, 256>>>(attn);

    fc_kernel<<<(B_ * L_) / 128, 256>>>(fc_w, fc_b, out);

    (void)in_sizes; (void)n_in; (void)out_size;
}

// round 17
// speedup vs baseline: 1.0979x; 1.0424x over previous
#include <cuda_runtime.h>
#include <cuda_fp16.h>
#include <cstdint>

// Problem constants
#define B_ 2
#define L_ 4096
#define D_ 512
#define H_ 8
#define BH_ (B_ * H_)

// E is scaled by 2^-6 before fp16 conversion (exp(S/8) can reach ~7e4 > fp16 max);
// the x64 is folded back into the O normalization.
#define ESCALE 0.015625f
#define EUNSCALE 64.0f

// ---------------------------------------------------------------------------
// Static device scratch (allocation-free).
// ---------------------------------------------------------------------------
__device__ __half g_Qhi[BH_ * L_ * 64];
__device__ __half g_Qlo[BH_ * L_ * 64];
__device__ __half g_Khi[BH_ * L_ * 64];
__device__ __half g_Klo[BH_ * L_ * 64];
__device__ __half g_Vhi[BH_ * L_ * 64];
__device__ __half g_Vlo[BH_ * L_ * 64];
__device__ __half g_Xhi[3][B_ * L_ * D_];   // fp16 hi/lo splits of inputs q,k,v
__device__ __half g_Xlo[3][B_ * L_ * D_];
__device__ __half g_Whi[3][D_ * D_];        // splits of wq,wk,wv
__device__ __half g_Wlo[3][D_ * D_];
__device__ __half g_FWhi[64 * D_];          // split of fc_w
__device__ __half g_FWlo[64 * D_];
__device__ __half g_Ohi[BH_ * L_ * 64];     // normalized context, fp16 hi/lo
__device__ __half g_Olo[BH_ * L_ * 64];
__device__ float  g_rowsum[BH_ * L_];       // 1/rowsum  [(h*B+b)][l]

// ---------------------------------------------------------------------------
// mma.sync / ldmatrix / cp.async helpers (base sm_103 features, no 'a')
// ---------------------------------------------------------------------------
__device__ __forceinline__ uint32_t smem_u32(const void* p) {
    uint32_t a;
    asm("{ .reg .u64 t; cvta.to.shared.u64 t, %1; cvt.u32.u64 %0, t; }"
        : "=r"(a) : "l"(p));
    return a;
}
__device__ __forceinline__ void ldm4(uint32_t* r, uint32_t a) {
    asm volatile("ldmatrix.sync.aligned.m8n8.x4.shared.b16 {%0,%1,%2,%3}, [%4];"
        : "=r"(r[0]), "=r"(r[1]), "=r"(r[2]), "=r"(r[3]) : "r"(a));
}
__device__ __forceinline__ void ldm4t(uint32_t* r, uint32_t a) {
    asm volatile("ldmatrix.sync.aligned.m8n8.x4.trans.shared.b16 {%0,%1,%2,%3}, [%4];"
        : "=r"(r[0]), "=r"(r[1]), "=r"(r[2]), "=r"(r[3]) : "r"(a));
}
__device__ __forceinline__ void mma16(float* d, const uint32_t* a, const uint32_t* b) {
    asm volatile("mma.sync.aligned.m16n8k16.row.col.f32.f16.f16.f32 "
        "{%0,%1,%2,%3}, {%4,%5,%6,%7}, {%8,%9}, {%0,%1,%2,%3};"
        : "+f"(d[0]), "+f"(d[1]), "+f"(d[2]), "+f"(d[3])
        : "r"(a[0]), "r"(a[1]), "r"(a[2]), "r"(a[3]), "r"(b[0]), "r"(b[1]));
}
__device__ __forceinline__ void cp16(uint32_t s, const void* g) {
    asm volatile("cp.async.cg.shared.global [%0], [%1], 16;" :: "r"(s), "l"(g) : "memory");
}
#define CP_COMMIT()  asm volatile("cp.async.commit_group;" ::: "memory")
#define CP_WAIT(n)   asm volatile("cp.async.wait_group %0;" :: "n"(n) : "memory")

// split a float pair into fp16 hi / lo packed b32 regs
__device__ __forceinline__ void split2(float a, float b, uint32_t& hi, uint32_t& lo) {
    __half ha = __float2half_rn(a), hb = __float2half_rn(b);
    __half la = __float2half_rn(a - __half2float(ha));
    __half lb = __float2half_rn(b - __half2float(hb));
    __half2 h = __halves2half2(ha, hb), l = __halves2half2(la, lb);
    hi = *(uint32_t*)&h; lo = *(uint32_t*)&l;
}
// pack a float pair to fp16x2 (single cvt)
__device__ __forceinline__ uint32_t pack2(float a, float b) {
    __half2 h = __floats2half2_rn(a, b);
    return *(uint32_t*)&h;
}

#define PITCH 72                         // halfs per smem row (144B, 16B-mult)
#define TILE_B (128 * PITCH * 2)         // 18432 bytes per 128x64 fp16 tile

// ---------------------------------------------------------------------------
// split helpers: fp32 -> fp16 hi/lo
// ---------------------------------------------------------------------------
__device__ __forceinline__ void do_split4(const float* __restrict__ src,
                                          __half* __restrict__ hi,
                                          __half* __restrict__ lo, int i)
{
    float4 v = ((const float4*)src)[i];
    __half h0 = __float2half_rn(v.x), h1 = __float2half_rn(v.y);
    __half h2 = __float2half_rn(v.z), h3 = __float2half_rn(v.w);
    __half l0 = __float2half_rn(v.x - __half2float(h0));
    __half l1 = __float2half_rn(v.y - __half2float(h1));
    __half l2 = __float2half_rn(v.z - __half2float(h2));
    __half l3 = __float2half_rn(v.w - __half2float(h3));
    __half2* hp = (__half2*)&hi[4 * (size_t)i];
    __half2* lp = (__half2*)&lo[4 * (size_t)i];
    hp[0] = __halves2half2(h0, h1); hp[1] = __halves2half2(h2, h3);
    lp[0] = __halves2half2(l0, l1); lp[1] = __halves2half2(l2, l3);
}

// batched X splits: grid.y selects q/k/v
__global__ __launch_bounds__(256) void split_x_kernel(
    const float* __restrict__ q, const float* __restrict__ k,
    const float* __restrict__ v, int n4)
{
    int i = blockIdx.x * blockDim.x + threadIdx.x;
    if (i >= n4) return;
    int s = blockIdx.y;
    const float* src = (s == 0) ? q : (s == 1) ? k : v;
    do_split4(src, g_Xhi[s], g_Xlo[s], i);
}

// batched W splits: grid.y selects wq/wk/wv
__global__ __launch_bounds__(256) void split_w_kernel(
    const float* __restrict__ wq, const float* __restrict__ wk,
    const float* __restrict__ wv, int n4)
{
    int i = blockIdx.x * blockDim.x + threadIdx.x;
    if (i >= n4) return;
    int s = blockIdx.y;
    const float* src = (s == 0) ? wq : (s == 1) ? wk : wv;
    do_split4(src, g_Whi[s], g_Wlo[s], i);
}

__global__ __launch_bounds__(256) void split_fcw_kernel(
    const float* __restrict__ fcw, int n4)
{
    int i = blockIdx.x * blockDim.x + threadIdx.x;
    if (i >= n4) return;
    do_split4(fcw, g_FWhi, g_FWlo, i);
}

// ---------------------------------------------------------------------------
// proj_mma: C = X @ W.T + bias -> fp16 hi/lo splits in head-major layout.
// M=8192, N=512, K=512.  CTA: 128x128, 8 warps (16 rows x 128 cols each).
// ---------------------------------------------------------------------------
#define PROJ_SMEM (8 * TILE_B + 512)

__global__ __launch_bounds__(256) void proj_mma(const float* __restrict__ bias, int sel)
{
    extern __shared__ __align__(128) char smem[];
    const uint32_t sb = smem_u32(smem);
    float* sbias = (float*)(smem + 8 * TILE_B);

    const __half* Xhi = g_Xhi[sel];
    const __half* Xlo = g_Xlo[sel];
    const __half* Whi = g_Whi[sel];
    const __half* Wlo = g_Wlo[sel];
    __half* Ohi = (sel == 0) ? g_Qhi : (sel == 1) ? g_Khi : g_Vhi;
    __half* Olo = (sel == 0) ? g_Qlo : (sel == 1) ? g_Klo : g_Vlo;

    const int n0 = blockIdx.x * 128;
    const int m0 = blockIdx.y * 128;
    const int tid = threadIdx.x, wid = tid >> 5, lane = tid & 31;
    const int r0 = wid * 16;

    if (tid < 128) sbias[tid] = bias[n0 + tid];

    const int l7 = lane & 7;
    const uint32_t a_off = (uint32_t)((r0 + l7 + ((lane & 8) ? 8 : 0)) * PITCH
                                      + ((lane & 16) ? 8 : 0)) * 2;
    const uint32_t bk_off = (uint32_t)((l7 + ((lane & 16) ? 8 : 0)) * PITCH
                                       + ((lane & 8) ? 8 : 0)) * 2;

    float S[16][4];
#pragma unroll
    for (int i = 0; i < 16; i++)
#pragma unroll
        for (int j = 0; j < 4; j++) S[i][j] = 0.f;

    auto prefetch = [&](int kc, uint32_t buf) {
#pragma unroll
        for (int t = 0; t < 4; t++) {
            int i = tid + t * 256;
            int row = i >> 3, c8 = i & 7;
            uint32_t so = (uint32_t)(row * PITCH + c8 * 8) * 2;
            size_t xg = ((size_t)(m0 + row) * 512 + kc * 64 + c8 * 8) * 2;
            size_t wg = ((size_t)(n0 + row) * 512 + kc * 64 + c8 * 8) * 2;
            cp16(buf + 0 * TILE_B + so, (const char*)Xhi + xg);
            cp16(buf + 1 * TILE_B + so, (const char*)Xlo + xg);
            cp16(buf + 2 * TILE_B + so, (const char*)Whi + wg);
            cp16(buf + 3 * TILE_B + so, (const char*)Wlo + wg);
        }
    };

    prefetch(0, sb);
    CP_COMMIT();

    for (int kc = 0; kc < 8; kc++) {
        const uint32_t buf = sb + ((kc & 1) ? 4 * TILE_B : 0);
        if (kc < 7) {
            prefetch(kc + 1, sb + (((kc + 1) & 1) ? 4 * TILE_B : 0));
            CP_COMMIT();
            CP_WAIT(1);
        } else {
            CP_WAIT(0);
        }
        __syncthreads();

#pragma unroll
        for (int ks = 0; ks < 4; ks++) {
            const uint32_t kc2 = (uint32_t)(ks * 16) * 2;
            uint32_t ah[4], al[4];
            ldm4(ah, buf + 0 * TILE_B + a_off + kc2);
            ldm4(al, buf + 1 * TILE_B + a_off + kc2);
#pragma unroll
            for (int np = 0; np < 8; np++) {
                uint32_t bh4[4], bl4[4];
                uint32_t boff = bk_off + (uint32_t)(np * 16 * PITCH) * 2 + kc2;
                ldm4(bh4, buf + 2 * TILE_B + boff);
                ldm4(bl4, buf + 3 * TILE_B + boff);
                mma16(S[2 * np],     ah, bh4 + 0);
                mma16(S[2 * np],     ah, bl4 + 0);
                mma16(S[2 * np],     al, bh4 + 0);
                mma16(S[2 * np + 1], ah, bh4 + 2);
                mma16(S[2 * np + 1], ah, bl4 + 2);
                mma16(S[2 * np + 1], al, bh4 + 2);
            }
        }
        __syncthreads();
    }

    const int row0 = m0 + r0 + (lane >> 2);
    const int row1 = row0 + 8;
    const int bb0 = row0 >> 12, l0r = row0 & (L_ - 1);
    const int bb1 = row1 >> 12, l1r = row1 & (L_ - 1);
#pragma unroll
    for (int nb = 0; nb < 16; nb++) {
        int col = nb * 8 + (lane & 3) * 2;
        int n = n0 + col;
        int hh = n >> 6, d = n & 63;
        float b0 = sbias[col], b1 = sbias[col + 1];
        float v00 = S[nb][0] + b0, v01 = S[nb][1] + b1;
        float v10 = S[nb][2] + b0, v11 = S[nb][3] + b1;
        uint32_t hi0, lo0, hi1, lo1;
        split2(v00, v01, hi0, lo0);
        split2(v10, v11, hi1, lo1);
        size_t off0 = (((size_t)(bb0 * H_ + hh)) * L_ + l0r) * 64 + d;
        size_t off1 = (((size_t)(bb1 * H_ + hh)) * L_ + l1r) * 64 + d;
        *(uint32_t*)&Ohi[off0] = hi0; *(uint32_t*)&Olo[off0] = lo0;
        *(uint32_t*)&Ohi[off1] = hi1; *(uint32_t*)&Olo[off1] = lo1;
    }
}

// ---------------------------------------------------------------------------
// HMMA attention: per CTA one (b,h,128 q-rows), sweep 32 k-tiles of 128.
// GEMM1 3-term fp16 split; GEMM2 2-term Ehi*(Vhi+Vlo).
// O emitted as fp16 hi/lo (for HMMA fc); g_rowsum stores 1/rowsum.
// ---------------------------------------------------------------------------
#define SM_QHI  0
#define SM_QLO  TILE_B
#define SM_KV0  (2 * TILE_B)             // buf0: Khi,Klo,Vhi,Vlo
#define SM_KV1  (6 * TILE_B)             // buf1
#define SM_RINV (10 * TILE_B)            // float rowinv[128]
#define ATTN_SMEM_BYTES (SM_RINV + 512)

__device__ __forceinline__ void prefetch_tile(uint32_t kv, int bh_in, int kt, int tid)
{
    const char* kh = (const char*)(g_Khi + ((size_t)bh_in * L_ + (size_t)kt * 128) * 64);
    const char* kl = (const char*)(g_Klo + ((size_t)bh_in * L_ + (size_t)kt * 128) * 64);
    const char* vh = (const char*)(g_Vhi + ((size_t)bh_in * L_ + (size_t)kt * 128) * 64);
    const char* vl = (const char*)(g_Vlo + ((size_t)bh_in * L_ + (size_t)kt * 128) * 64);
#pragma unroll
    for (int t = 0; t < 4; t++) {
        int i = tid + t * 256;               // 1024 16B chunks per tensor
        int row = i >> 3, c8 = i & 7;
        uint32_t so = (uint32_t)(row * PITCH + c8 * 8) * 2;
        size_t  go = (size_t)row * 128 + c8 * 16;
        cp16(kv + 0 * TILE_B + so, kh + go);
        cp16(kv + 1 * TILE_B + so, kl + go);
        cp16(kv + 2 * TILE_B + so, vh + go);
        cp16(kv + 3 * TILE_B + so, vl + go);
    }
}

__global__ __launch_bounds__(256) void attn_kernel(float* __restrict__ attn_out)
{
    extern __shared__ __align__(128) char smem[];
    const uint32_t sb = smem_u32(smem);
    float* rowinv = (float*)(smem + SM_RINV);

    const int qt = blockIdx.x, h = blockIdx.y, b = blockIdx.z;
    const int bh_in  = b * H_ + h;
    const int bh_out = h * B_ + b;
    const int tid = threadIdx.x, wid = tid >> 5, lane = tid & 31;
    const int r0 = wid * 16;

    // ---- load Q tile (plain) ----
    {
        const char* qh = (const char*)(g_Qhi + ((size_t)bh_in * L_ + (size_t)qt * 128) * 64);
        const char* ql = (const char*)(g_Qlo + ((size_t)bh_in * L_ + (size_t)qt * 128) * 64);
#pragma unroll
        for (int t = 0; t < 4; t++) {
            int i = tid + t * 256;
            int row = i >> 3, c8 = i & 7;
            uint32_t so = (uint32_t)(row * PITCH + c8 * 8) * 2;
            size_t  go = (size_t)row * 128 + c8 * 16;
            *(uint4*)(smem + SM_QHI + so) = *(const uint4*)(qh + go);
            *(uint4*)(smem + SM_QLO + so) = *(const uint4*)(ql + go);
        }
    }

    // ---- lane-invariant ldmatrix address offsets ----
    const int l7 = lane & 7;
    const uint32_t a_off = (uint32_t)((r0 + l7 + ((lane & 8) ? 8 : 0)) * PITCH
                                      + ((lane & 16) ? 8 : 0)) * 2;
    const uint32_t bk_off = (uint32_t)((l7 + ((lane & 16) ? 8 : 0)) * PITCH
                                       + ((lane & 8) ? 8 : 0)) * 2;
    const uint32_t bv_off = (uint32_t)((l7 + ((lane & 8) ? 8 : 0)) * PITCH
                                       + ((lane & 16) ? 8 : 0)) * 2;

    float* attn_base = attn_out + ((size_t)bh_out * L_ + (size_t)qt * 128) * L_;

    float Oa[8][4];
#pragma unroll
    for (int i = 0; i < 8; i++)
#pragma unroll
        for (int j = 0; j < 4; j++) Oa[i][j] = 0.f;
    float rs0 = 0.f, rs1 = 0.f;

    prefetch_tile(sb + SM_KV0, bh_in, 0, tid);
    CP_COMMIT();

    for (int kt = 0; kt < 32; kt++) {
        const uint32_t kv = sb + ((kt & 1) ? SM_KV1 : SM_KV0);
        if (kt < 31) {
            prefetch_tile(sb + (((kt + 1) & 1) ? SM_KV1 : SM_KV0), bh_in, kt + 1, tid);
            CP_COMMIT();
            CP_WAIT(1);
        } else {
            CP_WAIT(0);
        }
        __syncthreads();   // tile kt visible to all warps

        // ---- GEMM1: S[16x128] = Q @ K^T, 3-way fp16 split ----
        float S[16][4];
#pragma unroll
        for (int i = 0; i < 16; i++)
#pragma unroll
            for (int j = 0; j < 4; j++) S[i][j] = 0.f;

#pragma unroll
        for (int ks = 0; ks < 4; ks++) {
            const uint32_t kc2 = (uint32_t)(ks * 16) * 2;
            uint32_t ah[4], al[4];
            ldm4(ah, sb + SM_QHI + a_off + kc2);
            ldm4(al, sb + SM_QLO + a_off + kc2);
#pragma unroll
            for (int np = 0; np < 8; np++) {
                uint32_t bh4[4], bl4[4];
                uint32_t boff = bk_off + (uint32_t)(np * 16 * PITCH) * 2 + kc2;
                ldm4(bh4, kv + 0 * TILE_B + boff);
                ldm4(bl4, kv + 1 * TILE_B + boff);
                mma16(S[2 * np],     ah, bh4 + 0);
                mma16(S[2 * np],     ah, bl4 + 0);
                mma16(S[2 * np],     al, bh4 + 0);
                mma16(S[2 * np + 1], ah, bh4 + 2);
                mma16(S[2 * np + 1], ah, bl4 + 2);
                mma16(S[2 * np + 1], al, bh4 + 2);
            }
        }

        // ---- epilogue: exp, store E (fp32), rowsum; scale E for fp16 GEMM2 ----
        float* gp0 = attn_base + (size_t)(r0 + (lane >> 2)) * L_ + kt * 128 + (lane & 3) * 2;
        float* gp1 = gp0 + 8 * L_;
        float sum0 = 0.f, sum1 = 0.f;
#pragma unroll
        for (int nb = 0; nb < 16; nb++) {
            float e0 = __expf(S[nb][0] * 0.125f);
            float e1 = __expf(S[nb][1] * 0.125f);
            float e2 = __expf(S[nb][2] * 0.125f);
            float e3 = __expf(S[nb][3] * 0.125f);
            sum0 += e0 + e1; sum1 += e2 + e3;
            *(float2*)(gp0 + nb * 8) = make_float2(e0, e1);
            *(float2*)(gp1 + nb * 8) = make_float2(e2, e3);
            S[nb][0] = e0 * ESCALE; S[nb][1] = e1 * ESCALE;   // keep fp16 in range
            S[nb][2] = e2 * ESCALE; S[nb][3] = e3 * ESCALE;
        }
        sum0 += __shfl_xor_sync(0xFFFFFFFF, sum0, 1);
        sum0 += __shfl_xor_sync(0xFFFFFFFF, sum0, 2);
        sum1 += __shfl_xor_sync(0xFFFFFFFF, sum1, 1);
        sum1 += __shfl_xor_sync(0xFFFFFFFF, sum1, 2);
        rs0 += sum0; rs1 += sum1;

        // ---- GEMM2: O[16x64] += Ehi @ (Vhi + Vlo), A packed from registers ----
#pragma unroll
        for (int g = 0; g < 8; g++) {
            uint32_t ah[4];
            ah[0] = pack2(S[2 * g][0],     S[2 * g][1]);
            ah[1] = pack2(S[2 * g][2],     S[2 * g][3]);
            ah[2] = pack2(S[2 * g + 1][0], S[2 * g + 1][1]);
            ah[3] = pack2(S[2 * g + 1][2], S[2 * g + 1][3]);
            uint32_t vbase = bv_off + (uint32_t)(g * 16 * PITCH) * 2;
#pragma unroll
            for (int np = 0; np < 4; np++) {
                uint32_t vh4[4], vl4[4];
                uint32_t voff = vbase + (uint32_t)(np * 16) * 2;
                ldm4t(vh4, kv + 2 * TILE_B + voff);
                ldm4t(vl4, kv + 3 * TILE_B + voff);
                mma16(Oa[2 * np],     ah, vh4 + 0);
                mma16(Oa[2 * np],     ah, vl4 + 0);
                mma16(Oa[2 * np + 1], ah, vh4 + 2);
                mma16(Oa[2 * np + 1], ah, vl4 + 2);
            }
        }
        __syncthreads();   // all warps done reading buf before it is refilled
    }

    // ---- rowsum inverses: g_rowsum = 1/rs (norm uses directly), rowinv = 64/rs ----
    if ((lane & 3) == 0) {
        int rr = r0 + (lane >> 2);
        float i0 = 1.0f / rs0, i1 = 1.0f / rs1;
        g_rowsum[(size_t)bh_out * L_ + (size_t)qt * 128 + rr]     = i0;
        g_rowsum[(size_t)bh_out * L_ + (size_t)qt * 128 + rr + 8] = i1;
        rowinv[rr]     = EUNSCALE * i0;
        rowinv[rr + 8] = EUNSCALE * i1;
    }
    __syncthreads();

    // ---- normalize O, split to fp16 hi/lo, store ----
    {
        float i0 = rowinv[r0 + (lane >> 2)];
        float i1 = rowinv[r0 + (lane >> 2) + 8];
        size_t ob0 = ((size_t)bh_in * L_ + (size_t)qt * 128 + r0 + (lane >> 2)) * 64;
        size_t ob1 = ob0 + 8 * 64;
#pragma unroll
        for (int nb = 0; nb < 8; nb++) {
            int col = nb * 8 + (lane & 3) * 2;
            uint32_t h0, l0, h1, l1;
            split2(Oa[nb][0] * i0, Oa[nb][1] * i0, h0, l0);
            split2(Oa[nb][2] * i1, Oa[nb][3] * i1, h1, l1);
            *(uint32_t*)&g_Ohi[ob0 + col] = h0; *(uint32_t*)&g_Olo[ob0 + col] = l0;
            *(uint32_t*)&g_Ohi[ob1 + col] = h1; *(uint32_t*)&g_Olo[ob1 + col] = l1;
        }
    }
}

// ---------------------------------------------------------------------------
// Normalize attn in place:  attn[row][*] *= g_rowsum[row]  (already 1/rs)
// ---------------------------------------------------------------------------
__global__ __launch_bounds__(256) void norm_attn_kernel(float* __restrict__ attn)
{
    int i = blockIdx.x * blockDim.x + threadIdx.x;   // float4 index
    int row = i >> 10;                               // 1024 float4 per row
    float inv = g_rowsum[row];
    float4* p = (float4*)attn + i;
    float4 v = *p;
    v.x *= inv; v.y *= inv; v.z *= inv; v.w *= inv;
    *p = v;
}

// ---------------------------------------------------------------------------
// fc_mma: out = ctx @ fc_w.T + fc_b.  M=8192, N=64, K=512 (HMMA, 3-term).
// ctx(m,k): m=(b,l), k=(h,d) -> g_Ohi/[bh][l][d]; chunk kc == head kc.
// CTA: 128 rows x 64 cols, 8 warps (16 rows each, full N).
// ---------------------------------------------------------------------------
#define FC_BUF   (3 * TILE_B)            // Ohi(128) Olo(128) Whi(64) Wlo(64)
#define FC_SMEM  (2 * FC_BUF + 256)

__global__ __launch_bounds__(256) void fc_mma(const float* __restrict__ fc_b,
                                              float* __restrict__ out)
{
    extern __shared__ __align__(128) char smem[];
    const uint32_t sb = smem_u32(smem);
    float* sbias = (float*)(smem + 2 * FC_BUF);

    const int m0 = blockIdx.x * 128;
    const int tid = threadIdx.x, wid = tid >> 5, lane = tid & 31;
    const int r0 = wid * 16;
    const int bb = m0 >> 12;             // batch (tiles never straddle)

    if (tid < 64) sbias[tid] = fc_b[tid];

    const int l7 = lane & 7;
    const uint32_t a_off = (uint32_t)((r0 + l7 + ((lane & 8) ? 8 : 0)) * PITCH
                                      + ((lane & 16) ? 8 : 0)) * 2;
    const uint32_t bk_off = (uint32_t)((l7 + ((lane & 16) ? 8 : 0)) * PITCH
                                       + ((lane & 8) ? 8 : 0)) * 2;

    float S[8][4];
#pragma unroll
    for (int i = 0; i < 8; i++)
#pragma unroll
        for (int j = 0; j < 4; j++) S[i][j] = 0.f;

    auto prefetch = [&](int kc, uint32_t buf) {
        // A: 128 rows of head kc
        const __half* oh = g_Ohi + (((size_t)(bb * H_ + kc)) * L_ + (m0 & (L_ - 1))) * 64;
        const __half* ol = g_Olo + (((size_t)(bb * H_ + kc)) * L_ + (m0 & (L_ - 1))) * 64;
#pragma unroll
        for (int t = 0; t < 4; t++) {
            int i = tid + t * 256;           // 1024 chunks
            int row = i >> 3, c8 = i & 7;
            uint32_t so = (uint32_t)(row * PITCH + c8 * 8) * 2;
            size_t go = ((size_t)row * 64 + c8 * 8) * 2;
            cp16(buf + 0 * TILE_B + so, (const char*)oh + go);
            cp16(buf + 1 * TILE_B + so, (const char*)ol + go);
        }
        // B: 64 rows of fc_w, k-chunk kc
#pragma unroll
        for (int t = 0; t < 2; t++) {
            int i = tid + t * 256;           // 512 chunks
            int row = i >> 3, c8 = i & 7;
            uint32_t so = (uint32_t)(row * PITCH + c8 * 8) * 2;
            size_t wg = ((size_t)row * 512 + kc * 64 + c8 * 8) * 2;
            cp16(buf + 2 * TILE_B + so,                (const char*)g_FWhi + wg);
            cp16(buf + 2 * TILE_B + TILE_B / 2 + so,   (const char*)g_FWlo + wg);
        }
    };

    prefetch(0, sb);
    CP_COMMIT();

    for (int kc = 0; kc < 8; kc++) {
        const uint32_t buf = sb + ((kc & 1) ? FC_BUF : 0);
        if (kc < 7) {
            prefetch(kc + 1, sb + (((kc + 1) & 1) ? FC_BUF : 0));
            CP_COMMIT();
            CP_WAIT(1);
        } else {
            CP_WAIT(0);
        }
        __syncthreads();

#pragma unroll
        for (int ks = 0; ks < 4; ks++) {
            const uint32_t kc2 = (uint32_t)(ks * 16) * 2;
            uint32_t ah[4], al[4];
            ldm4(ah, buf + 0 * TILE_B + a_off + kc2);
            ldm4(al, buf + 1 * TILE_B + a_off + kc2);
#pragma unroll
            for (int np = 0; np < 4; np++) {
                uint32_t bh4[4], bl4[4];
                uint32_t boff = bk_off + (uint32_t)(np * 16 * PITCH) * 2 + kc2;
                ldm4(bh4, buf + 2 * TILE_B + boff);
                ldm4(bl4, buf + 2 * TILE_B + TILE_B / 2 + boff);
                mma16(S[2 * np],     ah, bh4 + 0);
                mma16(S[2 * np],     ah, bl4 + 0);
                mma16(S[2 * np],     al, bh4 + 0);
                mma16(S[2 * np + 1], ah, bh4 + 2);
                mma16(S[2 * np + 1], ah, bl4 + 2);
                mma16(S[2 * np + 1], al, bh4 + 2);
            }
        }
        __syncthreads();
    }

    const int row0 = m0 + r0 + (lane >> 2);
#pragma unroll
    for (int nb = 0; nb < 8; nb++) {
        int col = nb * 8 + (lane & 3) * 2;
        float b0 = sbias[col], b1 = sbias[col + 1];
        *(float2*)&out[(size_t)row0 * 64 + col] =
            make_float2(S[nb][0] + b0, S[nb][1] + b1);
        *(float2*)&out[(size_t)(row0 + 8) * 64 + col] =
            make_float2(S[nb][2] + b0, S[nb][3] + b1);
    }
}

// ---------------------------------------------------------------------------
// Launch
// ---------------------------------------------------------------------------
extern "C" void kernel_launch(void* const* d_in, const int* in_sizes, int n_in,
                              void* d_out, int out_size)
{
    const float* q    = (const float*)d_in[0];
    const float* k    = (const float*)d_in[1];
    const float* v    = (const float*)d_in[2];
    const float* wq   = (const float*)d_in[3];
    const float* bq   = (const float*)d_in[4];
    const float* wk   = (const float*)d_in[5];
    const float* bk   = (const float*)d_in[6];
    const float* wv   = (const float*)d_in[7];
    const float* bv   = (const float*)d_in[8];
    const float* fc_w = (const float*)d_in[9];
    const float* fc_b = (const float*)d_in[10];

    float* out  = (float*)d_out;                        // [B, L, DV]
    float* attn = out + (size_t)B_ * L_ * 64;           // [H*B, L, L]

    cudaFuncSetAttribute(attn_kernel,
                         cudaFuncAttributeMaxDynamicSharedMemorySize,
                         ATTN_SMEM_BYTES);
    cudaFuncSetAttribute(proj_mma,
                         cudaFuncAttributeMaxDynamicSharedMemorySize,
                         PROJ_SMEM);
    cudaFuncSetAttribute(fc_mma,
                         cudaFuncAttributeMaxDynamicSharedMemorySize,
                         FC_SMEM);

    const int NX = B_ * L_ * D_;         // 4,194,304
    const int NW = D_ * D_;              // 262,144
    const int NF = 64 * D_;              // 32,768

    dim3 sxg(NX / 4 / 256, 3);
    split_x_kernel<<<sxg, 256>>>(q, k, v, NX / 4);
    dim3 swg(NW / 4 / 256, 3);
    split_w_kernel<<<swg, 256>>>(wq, wk, wv, NW / 4);
    split_fcw_kernel<<<NF / 4 / 256, 256>>>(fc_w, NF / 4);

    dim3 pg(4, 64);
    proj_mma<<<pg, 256, PROJ_SMEM>>>(bq, 0);
    proj_mma<<<pg, 256, PROJ_SMEM>>>(bk, 1);
    proj_mma<<<pg, 256, PROJ_SMEM>>>(bv, 2);

    dim3 ag(L_ / 128, H_, B_);
    attn_kernel<<<ag, 256, ATTN_SMEM_BYTES>>>(attn);

    int n4 = BH_ * L_ * (L_ / 4);
    norm_attn_kernel<<<n4 / 256, 256>>>(attn);

    fc_mma<<<(B_ * L_) / 128, 256, FC_SMEM>>>(fc_b, out);

    (void)in_sizes; (void)n_in; (void)out_size;
}